// round 1
// baseline (speedup 1.0000x reference)
#include <cuda_runtime.h>

#define BATCH 2
#define NVERT 20000
#define NRINGS 8
#define NDIRS 8
#define CH 16
#define NF 16
#define VPB 16           // vertices per block
#define THREADS 256

// smem layout (floats)
#define SK_FLOATS (NRINGS*NDIRS*CH*NF)        // 16384
#define ZD_STRIDE 132                          // padded d-stride (floats), 16B aligned, bank-spread
#define ZV_STRIDE (NDIRS*ZD_STRIDE)            // 1056 per (b,v)
#define SZ_FLOATS (BATCH*VPB*ZV_STRIDE)        // 33792
#define SCK_FLOATS (CH*NF)                     // 256
#define SB_FLOATS  (NF)                        // 16
#define SMEM_FLOATS (SK_FLOATS + SZ_FLOATS + SCK_FLOATS + SB_FLOATS)
#define SMEM_BYTES  (SMEM_FLOATS * 4)

__global__ __launch_bounds__(THREADS, 1)
void geodesic_conv_kernel(const float* __restrict__ y,
                          const int*   __restrict__ contributors,
                          const float* __restrict__ weights_bary,
                          const int*   __restrict__ angles,
                          const float* __restrict__ kern,
                          const float* __restrict__ center_kernel,
                          const float* __restrict__ bias,
                          float*       __restrict__ out)
{
    extern __shared__ float smem[];
    float* sK  = smem;                 // [ (r*8+dw)*16 + c ][ f ] == input layout
    float* sZ  = sK + SK_FLOATS;       // [b][v][d][r][c] with padded strides
    float* sCK = sZ + SZ_FLOATS;       // [c][f]
    float* sB  = sCK + SCK_FLOATS;     // [f]

    const int tid = threadIdx.x;
    const int v0  = blockIdx.x * VPB;

    // ---- load conv kernel / center kernel / bias into smem ----
    {
        const float4* K4 = (const float4*)kern;
        float4* sK4 = (float4*)sK;
        #pragma unroll
        for (int i = 0; i < SK_FLOATS/4/THREADS; ++i)
            sK4[tid + i*THREADS] = K4[tid + i*THREADS];
        if (tid < SCK_FLOATS/4)
            ((float4*)sCK)[tid] = ((const float4*)center_kernel)[tid];
        if (tid < SB_FLOATS)
            sB[tid] = bias[tid];
    }

    // ---- gather phase: build z[b,v,r,d,c] in smem ----
    // thread-task decode: q (c-quad) fastest for coalesced 64B y reads
    const float4* y4 = (const float4*)y;
    {
        #pragma unroll 1
        for (int i = 0; i < (VPB*NRINGS*NDIRS*BATCH*4)/THREADS; ++i) {
            int g = tid + i*THREADS;              // 0..8191
            int q = g & 3;
            int b = (g >> 2) & 1;
            int r = (g >> 3) & 7;
            int d = (g >> 6) & 7;
            int v = (g >> 9) & (VPB-1);
            int ibase = (((v0 + v)*NRINGS + r)*NDIRS + d)*3;
            float4 acc = make_float4(0.f, 0.f, 0.f, 0.f);
            #pragma unroll
            for (int j = 0; j < 3; ++j) {
                int idx = contributors[ibase + j]*NDIRS + angles[ibase + j];
                float w = weights_bary[ibase + j];
                float4 p = __ldg(&y4[(b*NVERT*NDIRS + idx)*4 + q]);
                acc.x += w*p.x; acc.y += w*p.y; acc.z += w*p.z; acc.w += w*p.w;
            }
            *(float4*)&sZ[(b*VPB + v)*ZV_STRIDE + d*ZD_STRIDE + r*16 + q*4] = acc;
        }
    }
    __syncthreads();

    // ---- conv phase ----
    // thread -> (v, d) row + f-half; computes both batches (16 accumulators)
    const int rowid = tid >> 1;
    const int v  = rowid >> 3;
    const int d  = rowid & 7;
    const int fh = tid & 1;
    const int fbase = fh * 8;
    const int gv = v0 + v;

    float acc0[8], acc1[8];
    #pragma unroll
    for (int j = 0; j < 8; ++j) { acc0[j] = 0.f; acc1[j] = 0.f; }

    const float* z0base = sZ + v*ZV_STRIDE;
    const float* z1base = sZ + (VPB + v)*ZV_STRIDE;

    #pragma unroll 1
    for (int dw = 0; dw < 8; ++dw) {
        int dp = (d + dw) & 7;
        const float* z0 = z0base + dp*ZD_STRIDE;
        const float* z1 = z1base + dp*ZD_STRIDE;
        const float* kp = sK + dw*(CH*NF) + fbase;    // k row (r=0,c=0) for this dw
        #pragma unroll 1
        for (int r = 0; r < 8; ++r) {
            float zv0[16], zv1[16];
            #pragma unroll
            for (int q = 0; q < 4; ++q) {
                *(float4*)&zv0[q*4] = *(const float4*)(z0 + r*16 + q*4);
                *(float4*)&zv1[q*4] = *(const float4*)(z1 + r*16 + q*4);
            }
            const float* kr = kp + r*(NDIRS*CH*NF);   // + r*2048
            #pragma unroll
            for (int c = 0; c < 16; ++c) {
                float4 k0 = *(const float4*)(kr + c*NF);
                float4 k1 = *(const float4*)(kr + c*NF + 4);
                float a = zv0[c];
                float b = zv1[c];
                acc0[0] += a*k0.x; acc0[1] += a*k0.y; acc0[2] += a*k0.z; acc0[3] += a*k0.w;
                acc0[4] += a*k1.x; acc0[5] += a*k1.y; acc0[6] += a*k1.z; acc0[7] += a*k1.w;
                acc1[0] += b*k0.x; acc1[1] += b*k0.y; acc1[2] += b*k0.z; acc1[3] += b*k0.w;
                acc1[4] += b*k1.x; acc1[5] += b*k1.y; acc1[6] += b*k1.z; acc1[7] += b*k1.w;
            }
        }
    }

    // ---- center term: out += y[b,v,d,:] @ center_kernel ----
    {
        float cy0[16], cy1[16];
        const float4* yr0 = (const float4*)(y + ((0*NVERT + gv)*NDIRS + d)*CH);
        const float4* yr1 = (const float4*)(y + ((1*NVERT + gv)*NDIRS + d)*CH);
        #pragma unroll
        for (int q = 0; q < 4; ++q) {
            *(float4*)&cy0[q*4] = __ldg(&yr0[q]);
            *(float4*)&cy1[q*4] = __ldg(&yr1[q]);
        }
        #pragma unroll
        for (int c = 0; c < 16; ++c) {
            float4 k0 = *(const float4*)&sCK[c*NF + fbase];
            float4 k1 = *(const float4*)&sCK[c*NF + fbase + 4];
            float a = cy0[c];
            float b = cy1[c];
            acc0[0] += a*k0.x; acc0[1] += a*k0.y; acc0[2] += a*k0.z; acc0[3] += a*k0.w;
            acc0[4] += a*k1.x; acc0[5] += a*k1.y; acc0[6] += a*k1.z; acc0[7] += a*k1.w;
            acc1[0] += b*k0.x; acc1[1] += b*k0.y; acc1[2] += b*k0.z; acc1[3] += b*k0.w;
            acc1[4] += b*k1.x; acc1[5] += b*k1.y; acc1[6] += b*k1.z; acc1[7] += b*k1.w;
        }
    }

    // ---- bias, max over d (lane bits 1..3), relu, write ----
    float r0[8], r1[8];
    #pragma unroll
    for (int j = 0; j < 8; ++j) {
        float x0 = acc0[j] + sB[fbase + j];
        float x1 = acc1[j] + sB[fbase + j];
        #pragma unroll
        for (int m = 2; m <= 8; m <<= 1) {
            x0 = fmaxf(x0, __shfl_xor_sync(0xffffffffu, x0, m));
            x1 = fmaxf(x1, __shfl_xor_sync(0xffffffffu, x1, m));
        }
        r0[j] = fmaxf(x0, 0.f);
        r1[j] = fmaxf(x1, 0.f);
    }

    if (d == 0) {
        float4* o4 = (float4*)out;
        // out[b][gv][f], f-half fh
        o4[(0*NVERT + gv)*4 + fh*2 + 0] = *(float4*)&r0[0];
        o4[(0*NVERT + gv)*4 + fh*2 + 1] = *(float4*)&r0[4];
        o4[(1*NVERT + gv)*4 + fh*2 + 0] = *(float4*)&r1[0];
        o4[(1*NVERT + gv)*4 + fh*2 + 1] = *(float4*)&r1[4];
    }
}

extern "C" void kernel_launch(void* const* d_in, const int* in_sizes, int n_in,
                              void* d_out, int out_size)
{
    (void)in_sizes; (void)n_in; (void)out_size;
    const float* y            = (const float*)d_in[0];
    const int*   contributors = (const int*)  d_in[1];
    const float* weights_bary = (const float*)d_in[2];
    const int*   angles       = (const int*)  d_in[3];
    const float* kern         = (const float*)d_in[4];
    const float* center_k     = (const float*)d_in[5];
    const float* bias         = (const float*)d_in[6];
    float* out = (float*)d_out;

    cudaFuncSetAttribute(geodesic_conv_kernel,
                         cudaFuncAttributeMaxDynamicSharedMemorySize, SMEM_BYTES);

    dim3 grid(NVERT / VPB);   // 1250
    dim3 block(THREADS);
    geodesic_conv_kernel<<<grid, block, SMEM_BYTES>>>(
        y, contributors, weights_bary, angles, kern, center_k, bias, out);
}

// round 2
// speedup vs baseline: 1.3424x; 1.3424x over previous
#include <cuda_runtime.h>

#define BATCH 2
#define NVERT 20000
#define NRINGS 8
#define NDIRS 8
#define CH 16
#define NF 16
#define VPB 16           // vertices per block
#define THREADS 256

typedef unsigned long long ull;

// smem layout (floats)
#define SK_FLOATS (NRINGS*NDIRS*CH*NF)        // 16384
#define ZD_STRIDE 132                          // padded d-stride (floats)
#define ZV_STRIDE (NDIRS*ZD_STRIDE)            // 1056 per (b,v)
#define SZ_FLOATS (BATCH*VPB*ZV_STRIDE)        // 33792
#define SCK_FLOATS (CH*NF)                     // 256
#define SB_FLOATS  (NF)                        // 16
#define SMEM_FLOATS (SK_FLOATS + SZ_FLOATS + SCK_FLOATS + SB_FLOATS)
#define SMEM_BYTES  (SMEM_FLOATS * 4)

__device__ __forceinline__ ull pack2(float a, float b) {
    ull r; asm("mov.b64 %0, {%1, %2};" : "=l"(r) : "f"(a), "f"(b)); return r;
}
__device__ __forceinline__ float2 unpack2(ull v) {
    float2 r; asm("mov.b64 {%0, %1}, %2;" : "=f"(r.x), "=f"(r.y) : "l"(v)); return r;
}
__device__ __forceinline__ void fma2(ull& d, ull a, ull b) {
    asm("fma.rn.f32x2 %0, %1, %2, %0;" : "+l"(d) : "l"(a), "l"(b));
}

__global__ __launch_bounds__(THREADS, 1)
void geodesic_conv_kernel(const float* __restrict__ y,
                          const int*   __restrict__ contributors,
                          const float* __restrict__ weights_bary,
                          const int*   __restrict__ angles,
                          const float* __restrict__ kern,
                          const float* __restrict__ center_kernel,
                          const float* __restrict__ bias,
                          float*       __restrict__ out)
{
    extern __shared__ float smem[];
    float* sK  = smem;                 // [ (r*8+dw)*16 + c ][ f ] == input layout
    float* sZ  = sK + SK_FLOATS;       // [b][v][d][r][c] with padded strides
    float* sCK = sZ + SZ_FLOATS;       // [c][f]
    float* sB  = sCK + SCK_FLOATS;     // [f]

    const int tid = threadIdx.x;
    const int v0  = blockIdx.x * VPB;

    // ---- load conv kernel / center kernel / bias into smem ----
    {
        const float4* K4 = (const float4*)kern;
        float4* sK4 = (float4*)sK;
        #pragma unroll
        for (int i = 0; i < SK_FLOATS/4/THREADS; ++i)
            sK4[tid + i*THREADS] = K4[tid + i*THREADS];
        if (tid < SCK_FLOATS/4)
            ((float4*)sCK)[tid] = ((const float4*)center_kernel)[tid];
        if (tid < SB_FLOATS)
            sB[tid] = bias[tid];
    }

    // ---- gather phase: build z[b,v,d,r,c] in smem ----
    const float4* y4 = (const float4*)y;
    {
        #pragma unroll 4
        for (int i = 0; i < (VPB*NRINGS*NDIRS*BATCH*4)/THREADS; ++i) {
            int g = tid + i*THREADS;              // 0..8191
            int q = g & 3;
            int b = (g >> 2) & 1;
            int r = (g >> 3) & 7;
            int d = (g >> 6) & 7;
            int v = (g >> 9) & (VPB-1);
            int ibase = (((v0 + v)*NRINGS + r)*NDIRS + d)*3;
            float4 acc = make_float4(0.f, 0.f, 0.f, 0.f);
            #pragma unroll
            for (int j = 0; j < 3; ++j) {
                int idx = contributors[ibase + j]*NDIRS + angles[ibase + j];
                float w = weights_bary[ibase + j];
                float4 p = __ldg(&y4[(b*NVERT*NDIRS + idx)*4 + q]);
                acc.x += w*p.x; acc.y += w*p.y; acc.z += w*p.z; acc.w += w*p.w;
            }
            *(float4*)&sZ[(b*VPB + v)*ZV_STRIDE + d*ZD_STRIDE + r*16 + q*4] = acc;
        }
    }
    __syncthreads();

    // ---- conv phase ----
    // thread -> (v, d) row + f-half; computes both batches, 8+8 floats as f32x2
    const int rowid = tid >> 1;
    const int v  = rowid >> 3;
    const int d  = rowid & 7;
    const int fh = tid & 1;
    const int fbase = fh * 8;
    const int gv = v0 + v;

    ull acc0[4], acc1[4];
    #pragma unroll
    for (int j = 0; j < 4; ++j) { acc0[j] = 0ull; acc1[j] = 0ull; }

    const float* z0base = sZ + v*ZV_STRIDE;
    const float* z1base = sZ + (VPB + v)*ZV_STRIDE;

    #pragma unroll 1
    for (int dw = 0; dw < 8; ++dw) {
        int dp = (d + dw) & 7;
        const float* z0 = z0base + dp*ZD_STRIDE;
        const float* z1 = z1base + dp*ZD_STRIDE;
        const float* kp = sK + dw*(CH*NF) + fbase;    // K row (r=0,c=0) for this dw
        #pragma unroll 1
        for (int r = 0; r < 8; ++r) {
            float zv0[16], zv1[16];
            #pragma unroll
            for (int q = 0; q < 4; ++q) {
                *(float4*)&zv0[q*4] = *(const float4*)(z0 + r*16 + q*4);
                *(float4*)&zv1[q*4] = *(const float4*)(z1 + r*16 + q*4);
            }
            const float* kr = kp + r*(NDIRS*CH*NF);   // + r*2048
            #pragma unroll
            for (int c = 0; c < 16; ++c) {
                ulonglong2 kA = *(const ulonglong2*)(kr + c*NF);      // f[0..3] of half
                ulonglong2 kB = *(const ulonglong2*)(kr + c*NF + 4);  // f[4..7] of half
                ull aa = pack2(zv0[c], zv0[c]);
                ull bb = pack2(zv1[c], zv1[c]);
                fma2(acc0[0], aa, kA.x); fma2(acc0[1], aa, kA.y);
                fma2(acc0[2], aa, kB.x); fma2(acc0[3], aa, kB.y);
                fma2(acc1[0], bb, kA.x); fma2(acc1[1], bb, kA.y);
                fma2(acc1[2], bb, kB.x); fma2(acc1[3], bb, kB.y);
            }
        }
    }

    // ---- center term: out += y[b,v,d,:] @ center_kernel ----
    {
        float cy0[16], cy1[16];
        const float4* yr0 = (const float4*)(y + ((0*NVERT + gv)*NDIRS + d)*CH);
        const float4* yr1 = (const float4*)(y + ((1*NVERT + gv)*NDIRS + d)*CH);
        #pragma unroll
        for (int q = 0; q < 4; ++q) {
            *(float4*)&cy0[q*4] = __ldg(&yr0[q]);
            *(float4*)&cy1[q*4] = __ldg(&yr1[q]);
        }
        #pragma unroll
        for (int c = 0; c < 16; ++c) {
            ulonglong2 kA = *(const ulonglong2*)&sCK[c*NF + fbase];
            ulonglong2 kB = *(const ulonglong2*)&sCK[c*NF + fbase + 4];
            ull aa = pack2(cy0[c], cy0[c]);
            ull bb = pack2(cy1[c], cy1[c]);
            fma2(acc0[0], aa, kA.x); fma2(acc0[1], aa, kA.y);
            fma2(acc0[2], aa, kB.x); fma2(acc0[3], aa, kB.y);
            fma2(acc1[0], bb, kA.x); fma2(acc1[1], bb, kA.y);
            fma2(acc1[2], bb, kB.x); fma2(acc1[3], bb, kB.y);
        }
    }

    // ---- bias, max over d (lane bits 1..3), relu, write ----
    float r0[8], r1[8];
    #pragma unroll
    for (int j = 0; j < 4; ++j) {
        float2 x0 = unpack2(acc0[j]);
        float2 x1 = unpack2(acc1[j]);
        r0[j*2+0] = x0.x; r0[j*2+1] = x0.y;
        r1[j*2+0] = x1.x; r1[j*2+1] = x1.y;
    }
    #pragma unroll
    for (int j = 0; j < 8; ++j) {
        float x0 = r0[j] + sB[fbase + j];
        float x1 = r1[j] + sB[fbase + j];
        #pragma unroll
        for (int m = 2; m <= 8; m <<= 1) {
            x0 = fmaxf(x0, __shfl_xor_sync(0xffffffffu, x0, m));
            x1 = fmaxf(x1, __shfl_xor_sync(0xffffffffu, x1, m));
        }
        r0[j] = fmaxf(x0, 0.f);
        r1[j] = fmaxf(x1, 0.f);
    }

    if (d == 0) {
        float4* o4 = (float4*)out;
        o4[(0*NVERT + gv)*4 + fh*2 + 0] = *(float4*)&r0[0];
        o4[(0*NVERT + gv)*4 + fh*2 + 1] = *(float4*)&r0[4];
        o4[(1*NVERT + gv)*4 + fh*2 + 0] = *(float4*)&r1[0];
        o4[(1*NVERT + gv)*4 + fh*2 + 1] = *(float4*)&r1[4];
    }
}

extern "C" void kernel_launch(void* const* d_in, const int* in_sizes, int n_in,
                              void* d_out, int out_size)
{
    (void)in_sizes; (void)n_in; (void)out_size;
    const float* y            = (const float*)d_in[0];
    const int*   contributors = (const int*)  d_in[1];
    const float* weights_bary = (const float*)d_in[2];
    const int*   angles       = (const int*)  d_in[3];
    const float* kern         = (const float*)d_in[4];
    const float* center_k     = (const float*)d_in[5];
    const float* bias         = (const float*)d_in[6];
    float* out = (float*)d_out;

    cudaFuncSetAttribute(geodesic_conv_kernel,
                         cudaFuncAttributeMaxDynamicSharedMemorySize, SMEM_BYTES);

    dim3 grid(NVERT / VPB);   // 1250
    dim3 block(THREADS);
    geodesic_conv_kernel<<<grid, block, SMEM_BYTES>>>(
        y, contributors, weights_bary, angles, kern, center_k, bias, out);
}